// round 9
// baseline (speedup 1.0000x reference)
#include <cuda_runtime.h>
#include <math.h>

// out[b,c,p,n,q] = sum_h C[n,h] * x[b,c,p,h,q]  for p<26,q<26 ; else 0.
// C (32x64) = (M32^3)^T[:, :26] @ (M64^3)[:26, :]   (host-computed in double)
//
// R8: 8n x 8q register tile per thread, FMA2-packed over q. x streams
// global->register (prefetch depth 2, no smem, no barriers); only C is read
// from smem (delivered-bytes-cheap). 128-thread blocks, 4+/SM.

struct CtParam { float ct[64][32]; };   // ct[h][n]

#define FMA2(d, a, b)   asm("fma.rn.f32x2 %0, %1, %2, %0;" : "+l"(d) : "l"(a), "l"(b))
#define DUP2(d, f)      asm("mov.b64 %0, {%1, %1};" : "=l"(d) : "f"(f))
#define PACK2(d, lo, hi) asm("mov.b64 %0, {%1, %2};" : "=l"(d) : "f"(lo), "f"(hi))

#define LOADX(h, s) do {                                                        \
    if (pa) {                                                                   \
        va[s] = __ldcs(reinterpret_cast<const float4*>(xb + (size_t)(h) * 64)); \
        if (qtail) {                                                            \
            va[s].z = 0.f; va[s].w = 0.f;                                       \
            vb[s] = make_float4(0.f, 0.f, 0.f, 0.f);                            \
        } else {                                                                \
            vb[s] = __ldcs(reinterpret_cast<const float4*>(xb + (size_t)(h) * 64 + 4)); \
        }                                                                       \
    } else {                                                                    \
        va[s] = make_float4(0.f, 0.f, 0.f, 0.f);                                \
        vb[s] = make_float4(0.f, 0.f, 0.f, 0.f);                                \
    }                                                                           \
} while (0)

__global__ void __launch_bounds__(128, 4) spectral_pool_kernel(
    const float* __restrict__ x, float* __restrict__ out,
    const __grid_constant__ CtParam cp)
{
    __shared__ float sC[64][32];            // 8 KB

    const int tid = threadIdx.x;
    const int bc  = blockIdx.x >> 2;        // 0..255
    const int pq  = blockIdx.x & 3;         // p-tile of 8

    // C -> smem: 512 float4 / 128 threads = 4 each
    {
        const float4* src = reinterpret_cast<const float4*>(&cp.ct[0][0]);
        float4* dst = reinterpret_cast<float4*>(&sC[0][0]);
        dst[tid]       = src[tid];
        dst[tid + 128] = src[tid + 128];
        dst[tid + 256] = src[tid + 256];
        dst[tid + 384] = src[tid + 384];
    }
    __syncthreads();                        // the only barrier

    const int n0 = (tid & 3) * 8;           // 8 n-rows
    const int c  = tid >> 2;                // 0..31 column groups
    const int pl = c >> 2;                  // p_local 0..7
    const int q0 = (c & 3) * 8;             // q0 in {0,8,16,24}
    const int p  = pq * 8 + pl;

    const bool pa    = (p < 26);
    const bool qtail = (q0 == 24);          // q 26..31 must be zero

    const float* xb = x + (size_t)bc * 262144 + (size_t)p * 4096 + q0;

    unsigned long long acc[8][4];           // 8 n x 4 q-pairs (f32x2)
#pragma unroll
    for (int r = 0; r < 8; r++)
#pragma unroll
        for (int j = 0; j < 4; j++) acc[r][j] = 0ull;

    float4 va[2], vb[2];
    LOADX(0, 0);
    LOADX(1, 1);

#pragma unroll 4
    for (int h = 0; h < 64; h++) {
        const int s = h & 1;
        float4 x0 = va[s], x1 = vb[s];
        if (h < 62) LOADX(h + 2, s);        // prefetch depth 2

        unsigned long long b0, b1, b2, b3;
        PACK2(b0, x0.x, x0.y); PACK2(b1, x0.z, x0.w);
        PACK2(b2, x1.x, x1.y); PACK2(b3, x1.z, x1.w);

        float4 a0 = *reinterpret_cast<const float4*>(&sC[h][n0]);
        float4 a1 = *reinterpret_cast<const float4*>(&sC[h][n0 + 4]);
        float av[8] = {a0.x, a0.y, a0.z, a0.w, a1.x, a1.y, a1.z, a1.w};
#pragma unroll
        for (int r = 0; r < 8; r++) {
            unsigned long long ap;
            DUP2(ap, av[r]);
            FMA2(acc[r][0], ap, b0);
            FMA2(acc[r][1], ap, b1);
            FMA2(acc[r][2], ap, b2);
            FMA2(acc[r][3], ap, b3);
        }
    }

    // store 8 n-rows x 8 q (pad region p>=26 / q>=26 is exact zero)
    float* ob = out + (size_t)bc * 32768 + (size_t)p * 1024 + q0;
#pragma unroll
    for (int r = 0; r < 8; r++) {
        ulonglong2 s0, s1;
        s0.x = acc[r][0]; s0.y = acc[r][1];
        s1.x = acc[r][2]; s1.y = acc[r][3];
        __stcs(reinterpret_cast<ulonglong2*>(ob + (size_t)(n0 + r) * 32), s0);
        __stcs(reinterpret_cast<ulonglong2*>(ob + (size_t)(n0 + r) * 32 + 4), s1);
    }
}

// ---------------- host side ----------------

static void mm_d(const double* A, const double* B, double* C, int n)
{
    for (int i = 0; i < n; i++)
        for (int j = 0; j < n; j++) {
            double s = 0.0;
            for (int k = 0; k < n; k++) s += A[i * n + k] * B[k * n + j];
            C[i * n + j] = s;
        }
}

static void build_ct(CtParam* cp)
{
    static double M64[64 * 64], T64[64 * 64], P64[64 * 64];
    static double M32[32 * 32], T32[32 * 32], P32[32 * 32];

    const double PI = 3.14159265358979323846;
    for (int k = 0; k < 64; k++)
        for (int n = 0; n < 64; n++) {
            double v = sqrt(2.0 / 64.0) * cos(PI * (2.0 * n + 1.0) * k / 128.0);
            if (k == 0) v = 1.0 / 8.0;
            M64[k * 64 + n] = v;
        }
    for (int k = 0; k < 32; k++)
        for (int n = 0; n < 32; n++) {
            double v = sqrt(2.0 / 32.0) * cos(PI * (2.0 * n + 1.0) * k / 64.0);
            if (k == 0) v = 1.0 / sqrt(32.0);
            M32[k * 32 + n] = v;
        }

    mm_d(M64, M64, T64, 64);
    mm_d(T64, M64, P64, 64);     // M64^3
    mm_d(M32, M32, T32, 32);
    mm_d(T32, M32, P32, 32);     // M32^3

    for (int n = 0; n < 32; n++)
        for (int h = 0; h < 64; h++) {
            double s = 0.0;
            for (int k = 0; k < 26; k++)
                s += P32[k * 32 + n] * P64[k * 64 + h];
            cp->ct[h][n] = (float)s;
        }
}

extern "C" void kernel_launch(void* const* d_in, const int* in_sizes, int n_in,
                              void* d_out, int out_size)
{
    (void)in_sizes; (void)n_in; (void)out_size;
    const float* x = (const float*)d_in[0];
    float* out = (float*)d_out;

    static CtParam cp;
    build_ct(&cp);

    spectral_pool_kernel<<<1024, 128>>>(x, out, cp);
}

// round 10
// speedup vs baseline: 1.7921x; 1.7921x over previous
#include <cuda_runtime.h>
#include <math.h>

// out[b,c,p,n,q] = sum_h C[n,h] * x[b,c,p,h,q]  for p<26,q<26 ; else 0.
// C (32x64) = (M32^3)^T[:, :26] @ (M64^3)[:26, :]   (host-computed in double)
//
// R10: R5's chunked smem staging (batched MLP, double buffer, 1 sync/chunk)
// combined with R8's 8n x 8q FMA2 register tile (0.066 L1-wf per FMA2).

struct CtParam { float ct[64][32]; };   // ct[h][n]

#define FMA2(d, a, b)   asm("fma.rn.f32x2 %0, %1, %2, %0;" : "+l"(d) : "l"(a), "l"(b))
#define DUP2(d, f)      asm("mov.b64 %0, {%1, %1};" : "=l"(d) : "f"(f))

__global__ void __launch_bounds__(128, 4) spectral_pool_kernel(
    const float* __restrict__ x, float* __restrict__ out,
    const __grid_constant__ CtParam cp)
{
    __shared__ float sC[64][32];            // 8 KB
    __shared__ float sX[2][8][8][32];       // 16 KB : [buf][p][h][q]

    const int tid = threadIdx.x;
    const int bc  = blockIdx.x >> 2;        // 0..255
    const int pt  = blockIdx.x & 3;         // p-tile of 8

    // C -> smem (4 x float4 per thread)
    {
        const float4* src = reinterpret_cast<const float4*>(&cp.ct[0][0]);
        float4* dst = reinterpret_cast<float4*>(&sC[0][0]);
        dst[tid]       = src[tid];
        dst[tid + 128] = src[tid + 128];
        dst[tid + 256] = src[tid + 256];
        dst[tid + 384] = src[tid + 384];
    }

    // ---- load decomposition: 4 float4 per chunk (8p x 8h x 32q) ----
    // i = tid + j*128 : q4 = i&7, h = (i>>3)&7, pll = i>>6  (j -> pll = j*2 + (tid>>6))
    const int q4   = tid & 7;
    const int hld  = (tid >> 3) & 7;
    const int pld0 = tid >> 6;              // 0..1 ; pll_j = pld0 + 2*j
    const bool ldz = (q4 == 7);             // q 28..31 always zero
    const bool ldt = (q4 == 6);             // zero z,w (q 26,27)

    // ---- compute decomposition: 8 n x 8 q per thread ----
    const int n0 = (tid & 3) * 8;
    const int cg = tid >> 2;                // 0..31
    const int pl = cg >> 2;                 // p_local 0..7
    const int q0 = (cg & 3) * 8;
    const int p  = pt * 8 + pl;

    const float* xb = x + (size_t)bc * 262144 + (size_t)(pt * 8) * 4096;

    unsigned long long acc[8][4];           // 8 n x 4 q-pairs (f32x2)
#pragma unroll
    for (int r = 0; r < 8; r++)
#pragma unroll
        for (int j = 0; j < 4; j++) acc[r][j] = 0ull;

    float4 v[4];

#define LOADCHUNK(kc) do {                                                     \
    _Pragma("unroll")                                                          \
    for (int j = 0; j < 4; j++) {                                              \
        int pll = pld0 + 2 * j;                                                \
        v[j] = make_float4(0.f, 0.f, 0.f, 0.f);                                \
        if (!ldz && (pt * 8 + pll) < 26)                                       \
            v[j] = __ldcs(reinterpret_cast<const float4*>(                     \
                xb + (size_t)pll * 4096 + (size_t)((kc) * 8 + hld) * 64 + q4 * 4)); \
        if (ldt) { v[j].z = 0.f; v[j].w = 0.f; }                               \
    }                                                                          \
} while (0)

#define STORECHUNK(buf) do {                                                   \
    _Pragma("unroll")                                                          \
    for (int j = 0; j < 4; j++)                                                \
        *reinterpret_cast<float4*>(&sX[buf][pld0 + 2 * j][hld][q4 * 4]) = v[j];\
} while (0)

#define COMPUTE(buf, kc) do {                                                  \
    _Pragma("unroll")                                                          \
    for (int k = 0; k < 8; k++) {                                              \
        float4 a0 = *reinterpret_cast<const float4*>(&sC[(kc) * 8 + k][n0]);   \
        float4 a1 = *reinterpret_cast<const float4*>(&sC[(kc) * 8 + k][n0 + 4]);\
        ulonglong2 bA = *reinterpret_cast<const ulonglong2*>(&sX[buf][pl][k][q0]);\
        ulonglong2 bB = *reinterpret_cast<const ulonglong2*>(&sX[buf][pl][k][q0 + 4]);\
        float av[8] = {a0.x, a0.y, a0.z, a0.w, a1.x, a1.y, a1.z, a1.w};        \
        _Pragma("unroll")                                                      \
        for (int r = 0; r < 8; r++) {                                          \
            unsigned long long ap;                                             \
            DUP2(ap, av[r]);                                                   \
            FMA2(acc[r][0], ap, bA.x);                                         \
            FMA2(acc[r][1], ap, bA.y);                                         \
            FMA2(acc[r][2], ap, bB.x);                                         \
            FMA2(acc[r][3], ap, bB.y);                                         \
        }                                                                      \
    }                                                                          \
} while (0)

    // prologue: chunk 0
    LOADCHUNK(0);
    STORECHUNK(0);
    __syncthreads();                        // also covers the sC fill

    // kc loop: 8 chunks, 2-way unrolled for buffer parity; kcc dynamic
    for (int kcc = 0; kcc < 3; kcc++) {
        const int kc = kcc * 2;
        LOADCHUNK(kc + 1);
        COMPUTE(0, kc);
        STORECHUNK(1);
        __syncthreads();
        LOADCHUNK(kc + 2);
        COMPUTE(1, kc + 1);
        STORECHUNK(0);
        __syncthreads();
    }
    LOADCHUNK(7);
    COMPUTE(0, 6);
    STORECHUNK(1);
    __syncthreads();
    COMPUTE(1, 7);

    // store 8 n-rows x 8 q (pad region p>=26 / q>=26 is exact zero)
    float* ob = out + (size_t)bc * 32768 + (size_t)p * 1024 + q0;
#pragma unroll
    for (int r = 0; r < 8; r++) {
        ulonglong2 s0, s1;
        s0.x = acc[r][0]; s0.y = acc[r][1];
        s1.x = acc[r][2]; s1.y = acc[r][3];
        *reinterpret_cast<ulonglong2*>(ob + (size_t)(n0 + r) * 32)     = s0;
        *reinterpret_cast<ulonglong2*>(ob + (size_t)(n0 + r) * 32 + 4) = s1;
    }
}

// ---------------- host side ----------------

static void mm_d(const double* A, const double* B, double* C, int n)
{
    for (int i = 0; i < n; i++)
        for (int j = 0; j < n; j++) {
            double s = 0.0;
            for (int k = 0; k < n; k++) s += A[i * n + k] * B[k * n + j];
            C[i * n + j] = s;
        }
}

static void build_ct(CtParam* cp)
{
    static double M64[64 * 64], T64[64 * 64], P64[64 * 64];
    static double M32[32 * 32], T32[32 * 32], P32[32 * 32];

    const double PI = 3.14159265358979323846;
    for (int k = 0; k < 64; k++)
        for (int n = 0; n < 64; n++) {
            double v = sqrt(2.0 / 64.0) * cos(PI * (2.0 * n + 1.0) * k / 128.0);
            if (k == 0) v = 1.0 / 8.0;
            M64[k * 64 + n] = v;
        }
    for (int k = 0; k < 32; k++)
        for (int n = 0; n < 32; n++) {
            double v = sqrt(2.0 / 32.0) * cos(PI * (2.0 * n + 1.0) * k / 64.0);
            if (k == 0) v = 1.0 / sqrt(32.0);
            M32[k * 32 + n] = v;
        }

    mm_d(M64, M64, T64, 64);
    mm_d(T64, M64, P64, 64);     // M64^3
    mm_d(M32, M32, T32, 32);
    mm_d(T32, M32, P32, 32);     // M32^3

    for (int n = 0; n < 32; n++)
        for (int h = 0; h < 64; h++) {
            double s = 0.0;
            for (int k = 0; k < 26; k++)
                s += P32[k * 32 + n] * P64[k * 64 + h];
            cp->ct[h][n] = (float)s;
        }
}

extern "C" void kernel_launch(void* const* d_in, const int* in_sizes, int n_in,
                              void* d_out, int out_size)
{
    (void)in_sizes; (void)n_in; (void)out_size;
    const float* x = (const float*)d_in[0];
    float* out = (float*)d_out;

    static CtParam cp;
    build_ct(&cp);

    spectral_pool_kernel<<<1024, 128>>>(x, out, cp);
}

// round 12
// speedup vs baseline: 2.8603x; 1.5960x over previous
#include <cuda_runtime.h>
#include <math.h>

// out[b,c,p,n,q] = sum_h C[n,h] * x[b,c,p,h,q]  for p<26,q<26 ; else 0.
// C (32x64) = (M32^3)^T[:, :26] @ (M64^3)[:26, :]   (host-computed in double)
//
// R11: warp-uniform a-operand. Each warp owns one 8n block (lanes span 8p x 4q),
// so C comes from the param constant bank via dynamic-uniform LDC.128 (zero L1).
// x staged through swizzled smem chunks (16h, double-buffered). 0.25 L1-wf/FMA2.

struct CtParam { float ct[64][32]; };   // ct[h][n]

#define FMA2(d, a, b)   asm("fma.rn.f32x2 %0, %1, %2, %0;" : "+l"(d) : "l"(a), "l"(b))
#define DUP2(d, f)      asm("mov.b64 %0, {%1, %1};" : "=l"(d) : "f"(f))

__global__ void __launch_bounds__(256, 3) spectral_pool_kernel(
    const float* __restrict__ x, float* __restrict__ out,
    const __grid_constant__ CtParam cp)
{
    __shared__ float4 sX[2][16][8][8];      // [buf][h][p][slot] : 32 KB

    const int tid = threadIdx.x;
    const int bc  = blockIdx.x >> 2;        // 0..255
    const int pt  = blockIdx.x & 3;         // p-tile of 8

    // ---- loader decomposition: 4 float4 per 16h-chunk ----
    const int ls   = tid & 7;               // q float4-slot 0..7
    const int lp   = (tid >> 3) & 7;        // p_local (fixed per thread)
    const int lh0  = tid >> 6;              // h = lh0 + 4j
    const int lss  = ls ^ ((lp & 1) << 2);  // XOR swizzle (phase-conflict-free)
    const bool lz  = (ls == 7);             // q 28..31 -> 0
    const bool lt  = (ls == 6);             // q 26,27 -> 0
    const bool lpa = (pt * 8 + lp) < 26;

    // ---- compute decomposition: warp = 8n x 8p x 16q ; thread = 8n x 4q ----
    const int w    = tid >> 5;
    const int nb   = w & 3;                 // n-block  (n0 = nb*8)
    const int qh   = w >> 2;                // q-half   (q = qh*16 + qg*4)
    const int lane = tid & 31;
    const int pl   = lane >> 2;             // p_local 0..7
    const int qg   = lane & 3;
    const int slot = (qh * 4 + qg) ^ ((pl & 1) << 2);
    const int n0   = nb * 8;
    const int p    = pt * 8 + pl;

    const float* xb = x + (size_t)bc * 262144 + (size_t)lp * 4096 + ls * 4;
    const float4* cA = reinterpret_cast<const float4*>(&cp.ct[0][0]);  // param/const bank

    unsigned long long acc[8][2];           // 8 n x 2 q-pairs (f32x2)
#pragma unroll
    for (int r = 0; r < 8; r++) { acc[r][0] = 0ull; acc[r][1] = 0ull; }

    float4 v[4];

#define LOADCHUNK(kc) do {                                                     \
    _Pragma("unroll")                                                          \
    for (int j = 0; j < 4; j++) {                                              \
        v[j] = make_float4(0.f, 0.f, 0.f, 0.f);                                \
        if (!lz && lpa)                                                        \
            v[j] = __ldcs(reinterpret_cast<const float4*>(                     \
                xb + (size_t)(pt * 8) * 4096 +                                 \
                (size_t)((kc) * 16 + lh0 + 4 * j) * 64));                      \
        if (lt) { v[j].z = 0.f; v[j].w = 0.f; }                                \
    }                                                                          \
} while (0)

#define STORECHUNK(buf) do {                                                   \
    _Pragma("unroll")                                                          \
    for (int j = 0; j < 4; j++)                                                \
        sX[buf][lh0 + 4 * j][lp][lss] = v[j];                                  \
} while (0)

#define COMPUTE(buf, kc) do {                                                  \
    _Pragma("unroll")                                                          \
    for (int k = 0; k < 16; k++) {                                             \
        const int h = (kc) * 16 + k;                                           \
        float4 a0 = cA[h * 8 + nb * 2];        /* LDC.128, warp-uniform */     \
        float4 a1 = cA[h * 8 + nb * 2 + 1];                                    \
        ulonglong2 b = *reinterpret_cast<const ulonglong2*>(&sX[buf][k][pl][slot]); \
        float av[8] = {a0.x, a0.y, a0.z, a0.w, a1.x, a1.y, a1.z, a1.w};        \
        _Pragma("unroll")                                                      \
        for (int r = 0; r < 8; r++) {                                          \
            unsigned long long ap;                                             \
            DUP2(ap, av[r]);                                                   \
            FMA2(acc[r][0], ap, b.x);                                          \
            FMA2(acc[r][1], ap, b.y);                                          \
        }                                                                      \
    }                                                                          \
} while (0)

    // chunk pipeline: 4 chunks of 16h, double-buffered
    LOADCHUNK(0); STORECHUNK(0); __syncthreads();
    LOADCHUNK(1); COMPUTE(0, 0); STORECHUNK(1); __syncthreads();
    LOADCHUNK(2); COMPUTE(1, 1); STORECHUNK(0); __syncthreads();
    LOADCHUNK(3); COMPUTE(0, 2); STORECHUNK(1); __syncthreads();
    COMPUTE(1, 3);

    // store: 8 n-rows x 4 q (16B each); pad region p>=26 / q>=26 is exact zero
    float* ob = out + (size_t)bc * 32768 + (size_t)p * 1024 + qh * 16 + qg * 4;
#pragma unroll
    for (int r = 0; r < 8; r++) {
        ulonglong2 s;
        s.x = acc[r][0]; s.y = acc[r][1];
        *reinterpret_cast<ulonglong2*>(ob + (size_t)(n0 + r) * 32) = s;
    }
}

// ---------------- host side ----------------

static void mm_d(const double* A, const double* B, double* C, int n)
{
    for (int i = 0; i < n; i++)
        for (int j = 0; j < n; j++) {
            double s = 0.0;
            for (int k = 0; k < n; k++) s += A[i * n + k] * B[k * n + j];
            C[i * n + j] = s;
        }
}

static void build_ct(CtParam* cp)
{
    static double M64[64 * 64], T64[64 * 64], P64[64 * 64];
    static double M32[32 * 32], T32[32 * 32], P32[32 * 32];

    const double PI = 3.14159265358979323846;
    for (int k = 0; k < 64; k++)
        for (int n = 0; n < 64; n++) {
            double v = sqrt(2.0 / 64.0) * cos(PI * (2.0 * n + 1.0) * k / 128.0);
            if (k == 0) v = 1.0 / 8.0;
            M64[k * 64 + n] = v;
        }
    for (int k = 0; k < 32; k++)
        for (int n = 0; n < 32; n++) {
            double v = sqrt(2.0 / 32.0) * cos(PI * (2.0 * n + 1.0) * k / 64.0);
            if (k == 0) v = 1.0 / sqrt(32.0);
            M32[k * 32 + n] = v;
        }

    mm_d(M64, M64, T64, 64);
    mm_d(T64, M64, P64, 64);     // M64^3
    mm_d(M32, M32, T32, 32);
    mm_d(T32, M32, P32, 32);     // M32^3

    for (int n = 0; n < 32; n++)
        for (int h = 0; h < 64; h++) {
            double s = 0.0;
            for (int k = 0; k < 26; k++)
                s += P32[k * 32 + n] * P64[k * 64 + h];
            cp->ct[h][n] = (float)s;
        }
}

extern "C" void kernel_launch(void* const* d_in, const int* in_sizes, int n_in,
                              void* d_out, int out_size)
{
    (void)in_sizes; (void)n_in; (void)out_size;
    const float* x = (const float*)d_in[0];
    float* out = (float*)d_out;

    static CtParam cp;
    build_ct(&cp);

    spectral_pool_kernel<<<1024, 256>>>(x, out, cp);
}